// round 2
// baseline (speedup 1.0000x reference)
#include <cuda_runtime.h>
#include <cuda_bf16.h>
#include <cstdint>

// Problem shape (fixed by the dataset; N/E derived at launch from in_sizes)
#define MAX_NODES 170000
#define IN_DIM    64
#define OUT_DIM   40

// Scratch (device globals — no allocation allowed in kernel_launch)
__device__ float g_hp[(size_t)MAX_NODES * OUT_DIM];   // projected+pre-normed feats [N,40]
__device__ float g_norm[MAX_NODES];                   // rsqrt(max(deg,1))
__device__ float g_deg[MAX_NODES];                    // in-degree (float)

// ---------------------------------------------------------------------------
// K0: zero output accumulator and degree scratch
// ---------------------------------------------------------------------------
__global__ void k_zero(float* __restrict__ out, int out_n, int n_nodes) {
    int i = blockIdx.x * blockDim.x + threadIdx.x;
    int stride = gridDim.x * blockDim.x;
    for (int j = i; j < out_n; j += stride) out[j] = 0.0f;
    for (int j = i; j < n_nodes; j += stride) g_deg[j] = 0.0f;
}

// ---------------------------------------------------------------------------
// K1: in-degree via float atomics (exact for counts << 2^24)
// ---------------------------------------------------------------------------
__global__ void k_deg(const int* __restrict__ dst, int E) {
    int i = blockIdx.x * blockDim.x + threadIdx.x;
    int stride = gridDim.x * blockDim.x;
    for (int e = i; e < E; e += stride) {
        atomicAdd(&g_deg[dst[e]], 1.0f);
    }
}

// ---------------------------------------------------------------------------
// K2: hp[n,c] = rsqrt(max(deg[n],1)) * dot(feats[n,:], W[c,:]); also g_norm[n]
// Block: 320 threads = 40 cols x 8 node-groups; 32 nodes/block (4 nodes/thread)
// W transposed into smem (conflict-free reads), feats tiled into smem (pad 65).
// ---------------------------------------------------------------------------
__global__ void k_project(const float* __restrict__ feats,
                          const float* __restrict__ W, int N) {
    __shared__ float Wt[IN_DIM * OUT_DIM];   // Wt[d*40 + c]
    __shared__ float fs[32 * 65];            // fs[r*65 + d], padded stride

    const int tid = threadIdx.x;             // 0..319
    const int node0 = blockIdx.x * 32;

    // Load W [40,64] row-major -> transposed smem
    for (int i = tid; i < IN_DIM * OUT_DIM; i += 320) {
        int c = i / IN_DIM, d = i % IN_DIM;
        Wt[d * OUT_DIM + c] = W[i];
    }
    // Load up to 32 feat rows (coalesced)
    int nrows = N - node0; if (nrows > 32) nrows = 32;
    for (int i = tid; i < nrows * IN_DIM; i += 320) {
        int r = i / IN_DIM, d = i % IN_DIM;
        fs[r * 65 + d] = feats[(size_t)(node0 + r) * IN_DIM + d];
    }
    __syncthreads();

    const int c  = tid % OUT_DIM;   // column 0..39
    const int g0 = tid / OUT_DIM;   // node group 0..7
    float acc0 = 0.f, acc1 = 0.f, acc2 = 0.f, acc3 = 0.f;
#pragma unroll
    for (int d = 0; d < IN_DIM; d++) {
        float w = Wt[d * OUT_DIM + c];
        acc0 += fs[(g0 +  0) * 65 + d] * w;
        acc1 += fs[(g0 +  8) * 65 + d] * w;
        acc2 += fs[(g0 + 16) * 65 + d] * w;
        acc3 += fs[(g0 + 24) * 65 + d] * w;
    }
    float acc[4] = {acc0, acc1, acc2, acc3};
#pragma unroll
    for (int k = 0; k < 4; k++) {
        int n = node0 + g0 + 8 * k;
        if (n < N) {
            float nm = rsqrtf(fmaxf(g_deg[n], 1.0f));
            g_hp[(size_t)n * OUT_DIM + c] = acc[k] * nm;
            if (c == 0) g_norm[n] = nm;
        }
    }
}

// ---------------------------------------------------------------------------
// K3: edge scatter — out[dst,:] += hp[src,:], 40 floats/edge.
// float4 gathers (rows are 160B = 16B-aligned) + vector red.global.add.v2.f32.
// Working set (hp 27MB + out 27MB + edges 10MB) fits in the 126MB L2.
// ---------------------------------------------------------------------------
__device__ __forceinline__ void red_add_v2(float* addr, float x, float y) {
    asm volatile("red.global.add.v2.f32 [%0], {%1, %2};"
                 :: "l"(addr), "f"(x), "f"(y) : "memory");
}

__global__ void k_scatter(const int* __restrict__ src,
                          const int* __restrict__ dst,
                          float* __restrict__ out, int E) {
    int e = blockIdx.x * blockDim.x + threadIdx.x;
    if (e >= E) return;
    const int s = src[e];
    const int d = dst[e];
    const float4* __restrict__ hp4 =
        reinterpret_cast<const float4*>(g_hp + (size_t)s * OUT_DIM);
    float* op = out + (size_t)d * OUT_DIM;
#pragma unroll
    for (int k = 0; k < OUT_DIM / 4; k++) {   // 10 x float4
        float4 v = hp4[k];
        red_add_v2(op + 4 * k + 0, v.x, v.y);
        red_add_v2(op + 4 * k + 2, v.z, v.w);
    }
}

// ---------------------------------------------------------------------------
// K4: finalize — out[n,c] = out[n,c] * norm[n] + b[c]
// ---------------------------------------------------------------------------
__global__ void k_final(float* __restrict__ out, const float* __restrict__ b,
                        int total) {
    int i = blockIdx.x * blockDim.x + threadIdx.x;
    int stride = gridDim.x * blockDim.x;
    for (int j = i; j < total; j += stride) {
        int n = j / OUT_DIM;
        int c = j - n * OUT_DIM;
        out[j] = out[j] * g_norm[n] + __ldg(&b[c]);
    }
}

// ---------------------------------------------------------------------------
extern "C" void kernel_launch(void* const* d_in, const int* in_sizes, int n_in,
                              void* d_out, int out_size) {
    const float* feats = (const float*)d_in[0];
    const float* W     = (const float*)d_in[1];
    const float* b     = (const float*)d_in[2];
    const int*   src   = (const int*)d_in[3];   // JAX default x64-disabled -> int32
    const int*   dst   = (const int*)d_in[4];
    float* out = (float*)d_out;

    const int OUT = in_sizes[2];            // 40
    const int IN  = in_sizes[1] / OUT;      // 64
    const int N   = in_sizes[0] / IN;       // 170000
    const int E   = in_sizes[3];            // 1200000
    (void)n_in;

    // K0: zero out + deg
    {
        int total = out_size > N ? out_size : N;
        int blocks = (total + 255) / 256;
        if (blocks > 4096) blocks = 4096;
        k_zero<<<blocks, 256>>>(out, out_size, N);
    }
    // K1: degree
    {
        int blocks = (E + 255) / 256;
        k_deg<<<blocks, 256>>>(dst, E);
    }
    // K2: projection + norm
    {
        int blocks = (N + 31) / 32;
        k_project<<<blocks, 320>>>(feats, W, N);
    }
    // K3: scatter
    {
        int blocks = (E + 255) / 256;
        k_scatter<<<blocks, 256>>>(src, dst, out, E);
    }
    // K4: finalize
    {
        int blocks = (out_size + 255) / 256;
        if (blocks > 8192) blocks = 8192;
        k_final<<<blocks, 256>>>(out, b, out_size);
    }
}

// round 3
// speedup vs baseline: 1.3810x; 1.3810x over previous
#include <cuda_runtime.h>
#include <cuda_bf16.h>
#include <cstdint>

// Problem shape (fixed by the dataset; N/E derived at launch from in_sizes)
#define MAX_NODES 170000
#define IN_DIM    64
#define OUT_DIM   40

// Scratch (device globals — no allocation allowed in kernel_launch)
__device__ float g_hp[(size_t)MAX_NODES * OUT_DIM];   // projected+pre-normed feats [N,40]
__device__ float g_norm[MAX_NODES];                   // rsqrt(max(deg,1))
__device__ float g_deg[MAX_NODES];                    // in-degree (float)

// ---------------------------------------------------------------------------
// K0: zero output accumulator and degree scratch
// ---------------------------------------------------------------------------
__global__ void k_zero(float* __restrict__ out, int out_n, int n_nodes) {
    int i = blockIdx.x * blockDim.x + threadIdx.x;
    int stride = gridDim.x * blockDim.x;
    for (int j = i; j < out_n; j += stride) out[j] = 0.0f;
    for (int j = i; j < n_nodes; j += stride) g_deg[j] = 0.0f;
}

// ---------------------------------------------------------------------------
// K1: in-degree via float atomics (exact for counts << 2^24)
// ---------------------------------------------------------------------------
__global__ void k_deg(const int* __restrict__ dst, int E) {
    int i = blockIdx.x * blockDim.x + threadIdx.x;
    int stride = gridDim.x * blockDim.x;
    for (int e = i; e < E; e += stride) {
        atomicAdd(&g_deg[dst[e]], 1.0f);
    }
}

// ---------------------------------------------------------------------------
// K2: hp[n,c] = rsqrt(max(deg[n],1)) * dot(feats[n,:], W[c,:]); also g_norm[n]
// Block: 320 threads = 40 cols x 8 node-groups; 32 nodes/block (4 nodes/thread)
// ---------------------------------------------------------------------------
__global__ void k_project(const float* __restrict__ feats,
                          const float* __restrict__ W, int N) {
    __shared__ float Wt[IN_DIM * OUT_DIM];   // Wt[d*40 + c]
    __shared__ float fs[32 * 65];            // fs[r*65 + d], padded stride

    const int tid = threadIdx.x;             // 0..319
    const int node0 = blockIdx.x * 32;

    for (int i = tid; i < IN_DIM * OUT_DIM; i += 320) {
        int c = i / IN_DIM, d = i % IN_DIM;
        Wt[d * OUT_DIM + c] = W[i];
    }
    int nrows = N - node0; if (nrows > 32) nrows = 32;
    for (int i = tid; i < nrows * IN_DIM; i += 320) {
        int r = i / IN_DIM, d = i % IN_DIM;
        fs[r * 65 + d] = feats[(size_t)(node0 + r) * IN_DIM + d];
    }
    __syncthreads();

    const int c  = tid % OUT_DIM;   // column 0..39
    const int g0 = tid / OUT_DIM;   // node group 0..7
    float acc0 = 0.f, acc1 = 0.f, acc2 = 0.f, acc3 = 0.f;
#pragma unroll
    for (int d = 0; d < IN_DIM; d++) {
        float w = Wt[d * OUT_DIM + c];
        acc0 += fs[(g0 +  0) * 65 + d] * w;
        acc1 += fs[(g0 +  8) * 65 + d] * w;
        acc2 += fs[(g0 + 16) * 65 + d] * w;
        acc3 += fs[(g0 + 24) * 65 + d] * w;
    }
    float acc[4] = {acc0, acc1, acc2, acc3};
#pragma unroll
    for (int k = 0; k < 4; k++) {
        int n = node0 + g0 + 8 * k;
        if (n < N) {
            float nm = rsqrtf(fmaxf(g_deg[n], 1.0f));
            g_hp[(size_t)n * OUT_DIM + c] = acc[k] * nm;
            if (c == 0) g_norm[n] = nm;
        }
    }
}

// ---------------------------------------------------------------------------
// K3: edge scatter — out[dst,:] += hp[src,:], 40 floats/edge.
// Thread-per-(edge, float4-chunk): 10 consecutive lanes own one edge so both
// the gather LDG.128s and the RED.v4s cover the 160B row contiguously
// (sector-dense at LTS). 64 edges/block, 640 threads.
// ---------------------------------------------------------------------------
#define EDGES_PER_BLK 64
#define SCAT_THREADS  (EDGES_PER_BLK * 10)

__device__ __forceinline__ void red_add_v4(float* addr, float4 v) {
    asm volatile("red.global.add.v4.f32 [%0], {%1, %2, %3, %4};"
                 :: "l"(addr), "f"(v.x), "f"(v.y), "f"(v.z), "f"(v.w)
                 : "memory");
}

__global__ __launch_bounds__(SCAT_THREADS)
void k_scatter(const int* __restrict__ src,
               const int* __restrict__ dst,
               float* __restrict__ out, int E) {
    __shared__ int s_src[EDGES_PER_BLK];
    __shared__ int s_dst[EDGES_PER_BLK];

    const int tid = threadIdx.x;              // 0..639
    const int e0  = blockIdx.x * EDGES_PER_BLK;

    if (tid < EDGES_PER_BLK) {
        int e = e0 + tid;
        s_src[tid] = (e < E) ? src[e] : -1;
    } else if (tid < 2 * EDGES_PER_BLK) {
        int e = e0 + tid - EDGES_PER_BLK;
        s_dst[tid - EDGES_PER_BLK] = (e < E) ? dst[e] : -1;
    }
    __syncthreads();

    const int el = tid / 10;                  // local edge 0..63
    const int k  = tid % 10;                  // float4 chunk 0..9
    if (e0 + el >= E) return;

    const int s = s_src[el];
    const int d = s_dst[el];
    float4 v = reinterpret_cast<const float4*>(g_hp)[(size_t)s * 10 + k];
    red_add_v4(out + (size_t)d * OUT_DIM + k * 4, v);
}

// ---------------------------------------------------------------------------
// K4: finalize — out[n,c] = out[n,c] * norm[n] + b[c]
// ---------------------------------------------------------------------------
__global__ void k_final(float* __restrict__ out, const float* __restrict__ b,
                        int total) {
    int i = blockIdx.x * blockDim.x + threadIdx.x;
    int stride = gridDim.x * blockDim.x;
    for (int j = i; j < total; j += stride) {
        int n = j / OUT_DIM;
        int c = j - n * OUT_DIM;
        out[j] = out[j] * g_norm[n] + __ldg(&b[c]);
    }
}

// ---------------------------------------------------------------------------
extern "C" void kernel_launch(void* const* d_in, const int* in_sizes, int n_in,
                              void* d_out, int out_size) {
    const float* feats = (const float*)d_in[0];
    const float* W     = (const float*)d_in[1];
    const float* b     = (const float*)d_in[2];
    const int*   src   = (const int*)d_in[3];   // JAX x64 disabled -> int32
    const int*   dst   = (const int*)d_in[4];
    float* out = (float*)d_out;

    const int OUT = in_sizes[2];            // 40
    const int IN  = in_sizes[1] / OUT;      // 64
    const int N   = in_sizes[0] / IN;       // 170000
    const int E   = in_sizes[3];            // 1200000
    (void)n_in; (void)OUT;

    // K0: zero out + deg
    {
        int total = out_size > N ? out_size : N;
        int blocks = (total + 255) / 256;
        if (blocks > 4096) blocks = 4096;
        k_zero<<<blocks, 256>>>(out, out_size, N);
    }
    // K1: degree
    {
        int blocks = (E + 255) / 256;
        k_deg<<<blocks, 256>>>(dst, E);
    }
    // K2: projection + norm
    {
        int blocks = (N + 31) / 32;
        k_project<<<blocks, 320>>>(feats, W, N);
    }
    // K3: scatter (10 threads per edge)
    {
        int blocks = (E + EDGES_PER_BLK - 1) / EDGES_PER_BLK;
        k_scatter<<<blocks, SCAT_THREADS>>>(src, dst, out, E);
    }
    // K4: finalize
    {
        int blocks = (out_size + 255) / 256;
        if (blocks > 8192) blocks = 8192;
        k_final<<<blocks, 256>>>(out, b, out_size);
    }
}

// round 4
// speedup vs baseline: 1.9204x; 1.3906x over previous
#include <cuda_runtime.h>
#include <cuda_bf16.h>
#include <cstdint>

#define MAX_NODES 170000
#define IN_DIM    64
#define OUT_DIM   40

// Scratch (device globals — no allocation allowed in kernel_launch)
__device__ float g_hp[(size_t)MAX_NODES * OUT_DIM];   // projected+pre-normed feats [N,40]
__device__ float g_norm[MAX_NODES];                   // rsqrt(max(deg,1))
__device__ float g_deg[MAX_NODES];                    // in-degree; zero at entry (see k_final)

// ---------------------------------------------------------------------------
// K1: zero out[] (float4) + in-degree atomics. g_deg is already zero: it is
// zero-initialized at module load, and k_final re-zeroes it after its last use
// each run, so every graph replay starts from the same state.
// ---------------------------------------------------------------------------
__global__ void k_deg_zero(const int* __restrict__ dst, int E,
                           float4* __restrict__ out4, int out_n4) {
    int i = blockIdx.x * blockDim.x + threadIdx.x;
    int stride = gridDim.x * blockDim.x;
    const float4 z = make_float4(0.f, 0.f, 0.f, 0.f);
    for (int j = i; j < out_n4; j += stride) out4[j] = z;
    for (int e = i; e < E; e += stride) atomicAdd(&g_deg[dst[e]], 1.0f);
}

// ---------------------------------------------------------------------------
// K2: hp[n,c] = rsqrt(max(deg[n],1)) * dot(feats[n,:], W[c,:]); also g_norm[n]
// 320 threads = 40 cols x 8 node-groups; 32 nodes/block, 4 nodes/thread.
// Stride-68 smem padding -> float4 LDS for both W row and feat rows.
// Feat LDS broadcast across lanes sharing g0; W LDS.128 conflict-free
// (stride 17 x 16B across lanes).
// ---------------------------------------------------------------------------
__global__ __launch_bounds__(320)
void k_project(const float* __restrict__ feats,
               const float* __restrict__ W, int N) {
    __shared__ float W2[OUT_DIM * 68];   // W2[c*68 + d] (padded copy of W)
    __shared__ float fs[32 * 68];        // fs[r*68 + d]

    const int tid = threadIdx.x;         // 0..319
    const int node0 = blockIdx.x * 32;

    for (int i = tid; i < OUT_DIM * IN_DIM; i += 320) {
        int c = i >> 6, d = i & 63;
        W2[c * 68 + d] = W[i];
    }
    int nrows = N - node0; if (nrows > 32) nrows = 32;
    for (int i = tid; i < nrows * IN_DIM; i += 320) {
        int r = i >> 6, d = i & 63;
        fs[r * 68 + d] = feats[(size_t)(node0 + r) * IN_DIM + d];
    }
    __syncthreads();

    const int c  = tid % OUT_DIM;        // column 0..39
    const int g0 = tid / OUT_DIM;        // node group 0..7
    float acc0 = 0.f, acc1 = 0.f, acc2 = 0.f, acc3 = 0.f;
#pragma unroll
    for (int d = 0; d < IN_DIM; d += 4) {
        float4 w  = *reinterpret_cast<const float4*>(&W2[c * 68 + d]);
        float4 f0 = *reinterpret_cast<const float4*>(&fs[(g0 +  0) * 68 + d]);
        float4 f1 = *reinterpret_cast<const float4*>(&fs[(g0 +  8) * 68 + d]);
        float4 f2 = *reinterpret_cast<const float4*>(&fs[(g0 + 16) * 68 + d]);
        float4 f3 = *reinterpret_cast<const float4*>(&fs[(g0 + 24) * 68 + d]);
        acc0 += f0.x * w.x + f0.y * w.y + f0.z * w.z + f0.w * w.w;
        acc1 += f1.x * w.x + f1.y * w.y + f1.z * w.z + f1.w * w.w;
        acc2 += f2.x * w.x + f2.y * w.y + f2.z * w.z + f2.w * w.w;
        acc3 += f3.x * w.x + f3.y * w.y + f3.z * w.z + f3.w * w.w;
    }
    float acc[4] = {acc0, acc1, acc2, acc3};
#pragma unroll
    for (int k = 0; k < 4; k++) {
        int n = node0 + g0 + 8 * k;
        if (n < N) {
            float nm = rsqrtf(fmaxf(g_deg[n], 1.0f));
            g_hp[(size_t)n * OUT_DIM + c] = acc[k] * nm;
            if (c == 0) g_norm[n] = nm;
        }
    }
}

// ---------------------------------------------------------------------------
// K3: edge scatter — out[dst,:] += hp[src,:], 40 floats/edge.
// 5 lanes per edge, 2 float4 chunks per lane (ILP=2). No smem, no barrier:
// index loads from 5 lanes hit the same address (broadcast) and coalesce.
// Both gathers and REDs cover each 160B row contiguously (sector-dense).
// ---------------------------------------------------------------------------
__device__ __forceinline__ void red_add_v4(float* addr, float4 v) {
    asm volatile("red.global.add.v4.f32 [%0], {%1, %2, %3, %4};"
                 :: "l"(addr), "f"(v.x), "f"(v.y), "f"(v.z), "f"(v.w)
                 : "memory");
}

__global__ __launch_bounds__(640)
void k_scatter(const int* __restrict__ src,
               const int* __restrict__ dst,
               float* __restrict__ out, int E) {
    const int gt = blockIdx.x * 640 + threadIdx.x;
    const int e  = gt / 5;
    const int k  = gt - e * 5;           // chunk 0..4 (owns chunks k and k+5)
    if (e >= E) return;

    const int s = __ldg(&src[e]);
    const int d = __ldg(&dst[e]);
    const float4* __restrict__ hp4 =
        reinterpret_cast<const float4*>(g_hp) + (size_t)s * 10;
    float* op = out + (size_t)d * OUT_DIM;

    float4 v0 = hp4[k];
    float4 v1 = hp4[k + 5];
    red_add_v4(op + 4 * k, v0);
    red_add_v4(op + 4 * (k + 5), v1);
}

// ---------------------------------------------------------------------------
// K4: finalize — out[n,c] = out[n,c]*norm[n] + b[c] (float4), and re-zero
// g_deg for the next graph replay (deterministic: every run ends zeroed).
// ---------------------------------------------------------------------------
__global__ void k_final(float4* __restrict__ out4, const float4* __restrict__ b4,
                        int total4, int n_nodes) {
    int i = blockIdx.x * blockDim.x + threadIdx.x;
    int stride = gridDim.x * blockDim.x;
    for (int j = i; j < total4; j += stride) {
        int n = j / 10;                  // 10 float4 per row
        int q = j - n * 10;
        float nm = g_norm[n];
        float4 o = out4[j];
        float4 bb = __ldg(&b4[q]);
        o.x = o.x * nm + bb.x;
        o.y = o.y * nm + bb.y;
        o.z = o.z * nm + bb.z;
        o.w = o.w * nm + bb.w;
        out4[j] = o;
    }
    for (int j = i; j < n_nodes; j += stride) g_deg[j] = 0.0f;
}

// ---------------------------------------------------------------------------
extern "C" void kernel_launch(void* const* d_in, const int* in_sizes, int n_in,
                              void* d_out, int out_size) {
    const float* feats = (const float*)d_in[0];
    const float* W     = (const float*)d_in[1];
    const float* b     = (const float*)d_in[2];
    const int*   src   = (const int*)d_in[3];   // JAX x64 disabled -> int32
    const int*   dst   = (const int*)d_in[4];
    float* out = (float*)d_out;

    const int OUT = in_sizes[2];            // 40
    const int IN  = in_sizes[1] / OUT;      // 64
    const int N   = in_sizes[0] / IN;       // 170000
    const int E   = in_sizes[3];            // 1200000
    (void)n_in; (void)OUT;

    // K1: zero out + degree atomics
    k_deg_zero<<<2048, 256>>>(dst, E, (float4*)out, out_size / 4);

    // K2: projection + norm
    k_project<<<(N + 31) / 32, 320>>>(feats, W, N);

    // K3: scatter (5 threads x 2 chunks per edge)
    {
        long long total = (long long)E * 5;
        int blocks = (int)((total + 639) / 640);
        k_scatter<<<blocks, 640>>>(src, dst, out, E);
    }

    // K4: finalize + re-zero g_deg for next replay
    k_final<<<2048, 256>>>((float4*)out, (const float4*)b, out_size / 4, N);
}